// round 11
// baseline (speedup 1.0000x reference)
#include <cuda_runtime.h>
#include <cuda_fp16.h>
#include <cstdint>
#include <cstddef>

// ---------------- problem sizes ----------------
#define G_M    32768            // B*S = 16*2048
#define G_DIN  1024
#define G_DH   2048
#define G_DACT 1024

// ---------------- GEMM tiling ----------------
#define BM 128
#define BN 256
#define BK 64                   // halves per K-slice: 128 bytes/row
#define STAGES 3
#define NTHREADS 256

#define A_STAGE_HALFS (BM*BK)             // 8192 halves = 16 KB
#define B_STAGE_HALFS (BN*BK)             // 16384 halves = 32 KB
#define STAGE_HALFS   (A_STAGE_HALFS + B_STAGE_HALFS)
#define STAGE_BYTES   (STAGE_HALFS*2)     // 49152
#define SMEM_BYTES    (STAGES*STAGE_BYTES)// 147456

// ---------------- scratch (no cudaMalloc allowed) ----------------
__device__ __align__(16) __half g_xh [(size_t)G_M * G_DIN];     // 64 MB
__device__ __align__(16) __half g_h  [(size_t)G_M * G_DH];      // 128 MB
__device__ __align__(16) __half g_s2 [(size_t)G_M * G_DH];      // 128 MB
__device__ __align__(16) __half g_w1 [(size_t)G_DH * G_DIN];
__device__ __align__(16) __half g_w2 [(size_t)G_DH * G_DH];
__device__ __align__(16) __half g_w3 [(size_t)G_DACT * G_DH];

// ---------------- PTX helpers (base ISA only — no tcgen05 on .target sm_103) ----
__device__ __forceinline__ uint32_t smem_u32(const void* p) {
    uint32_t a;
    asm("{ .reg .u64 t; cvta.to.shared.u64 t, %1; cvt.u32.u64 %0, t; }" : "=r"(a) : "l"(p));
    return a;
}

#define CP_ASYNC16(sm, g) \
    asm volatile("cp.async.cg.shared.global [%0], [%1], 16;" :: "r"(sm), "l"(g))
#define CP_COMMIT() asm volatile("cp.async.commit_group;" ::: "memory")
#define CP_WAIT(n)  asm volatile("cp.async.wait_group %0;" :: "n"(n) : "memory")

// mma.sync m16n8k16 fp16 -> fp32 accumulate. Base ISA (sm_80+), legal on sm_103.
__device__ __forceinline__ void mma_f16(float* d, const uint32_t* a, const uint32_t* b) {
    asm volatile(
        "mma.sync.aligned.m16n8k16.row.col.f32.f16.f16.f32 "
        "{%0,%1,%2,%3}, {%4,%5,%6,%7}, {%8,%9}, {%0,%1,%2,%3};"
        : "+f"(d[0]), "+f"(d[1]), "+f"(d[2]), "+f"(d[3])
        : "r"(a[0]), "r"(a[1]), "r"(a[2]), "r"(a[3]), "r"(b[0]), "r"(b[1]));
}

// ldmatrix x4: 4 m8n8 fp16 matrices; lane L supplies row address for matrix L/8, row L%8.
__device__ __forceinline__ void ldsm_x4(uint32_t* r, uint32_t addr) {
    asm volatile(
        "ldmatrix.sync.aligned.m8n8.x4.shared.b16 {%0,%1,%2,%3}, [%4];"
        : "=r"(r[0]), "=r"(r[1]), "=r"(r[2]), "=r"(r[3]) : "r"(addr));
}

// ---------------- fp32 -> fp16 (RNE) conversion ----------------
__global__ void k_f32_to_f16(const float4* __restrict__ in, uint2* __restrict__ out, int n4) {
    for (int i = blockIdx.x * blockDim.x + threadIdx.x; i < n4; i += gridDim.x * blockDim.x) {
        float4 v = in[i];
        __half2 lo = __floats2half2_rn(v.x, v.y);
        __half2 hi = __floats2half2_rn(v.z, v.w);
        uint2 o;
        o.x = *reinterpret_cast<uint32_t*>(&lo);
        o.y = *reinterpret_cast<uint32_t*>(&hi);
        out[i] = o;
    }
}

// ---- fp16 mma.sync GEMM: C[M,N] = A[M,K] @ Bw[N,K]^T (+bias[,+bias2], relu) ----
// Block tile 128x256, 8 warps in 2(m) x 4(n), warp tile 64x64.
// OUT32=false: C is __half (RNE convert = rounding for the next GEMM's inputs).
// OUT32=true : C is float (final output).
template<bool RELU, bool HASB2, bool OUT32>
__global__ void __launch_bounds__(NTHREADS, 1)
gemm_f16(const __half* __restrict__ A, const __half* __restrict__ Bw,
         const float* __restrict__ bias, const float* __restrict__ bias2,
         void* __restrict__ Cv, int K, int ldc)
{
    extern __shared__ __half smem[];
    const uint32_t sbase = smem_u32(smem);
    const int tid = threadIdx.x;
    const int wid = tid >> 5;
    const int lid = tid & 31;
    const int m0 = blockIdx.y * BM;
    const int n0 = blockIdx.x * BN;
    const int kt = K / BK;

    // warp grid 2(m) x 4(n): warp tile 64m x 64n
    const int wm  = wid >> 2;         // 0..1
    const int wn  = wid & 3;          // 0..3
    const int g   = lid >> 2;         // 0..7
    const int tig = lid & 3;          // 0..3
    const int t2  = tig << 1;

    // ---- ldmatrix per-lane row precompute ----
    const int mi   = lid >> 3;        // matrix index 0..3
    const int mrow = lid & 7;         // row within matrix
    // A x4 (per i): {rows+0..7 klo, rows+8..15 klo, rows+0..7 khi, rows+8..15 khi}
    const int a_row_base = wm * 64 + ((mi & 1) << 3) + mrow;
    const uint32_t a_cadd = (uint32_t)(mi >> 1);
    // B x4 (per jp in 0..3): {j0 klo, j0 khi, j1 klo, j1 khi}; n-tile pair per jp
    const int b_row_base = wn * 64 + ((mi >> 1) << 3) + mrow;
    const uint32_t b_cadd = (uint32_t)(mi & 1);

    // loader mapping: rows x 8 chunks(16B); 256 threads -> 32 rows/pass
    const int lr = tid >> 3;          // 0..31
    const int lc = tid & 7;           // 0..7

    auto load_stage = [&](int slot, int it) {
        const int k0 = it * BK;
        const uint32_t sA = sbase + (uint32_t)slot * STAGE_BYTES;
        const uint32_t sB = sA + A_STAGE_HALFS * 2;
        const __half* gA = A  + (size_t)(m0 + lr) * K + k0 + (lc << 3);
        const __half* gB = Bw + (size_t)(n0 + lr) * K + k0 + (lc << 3);
        #pragma unroll
        for (int j = 0; j < BM / 32; ++j) {      // 4 passes for A (128 rows)
            const int row = lr + 32 * j;
            const uint32_t off = (uint32_t)(row * 128 + ((lc ^ (row & 7)) << 4));
            CP_ASYNC16(sA + off, gA + (size_t)(32 * j) * K);
        }
        #pragma unroll
        for (int j = 0; j < BN / 32; ++j) {      // 8 passes for B (256 rows)
            const int row = lr + 32 * j;
            const uint32_t off = (uint32_t)(row * 128 + ((lc ^ (row & 7)) << 4));
            CP_ASYNC16(sB + off, gB + (size_t)(32 * j) * K);
        }
    };

    float acc[4][8][4];
    #pragma unroll
    for (int i = 0; i < 4; ++i)
        #pragma unroll
        for (int j = 0; j < 8; ++j)
            #pragma unroll
            for (int e = 0; e < 4; ++e) acc[i][j][e] = 0.0f;

    #pragma unroll
    for (int s = 0; s < STAGES - 1; ++s) { load_stage(s, s); CP_COMMIT(); }

    for (int it = 0; it < kt; ++it) {
        CP_WAIT(STAGES - 2);
        __syncthreads();

        const int nxt = it + STAGES - 1;
        if (nxt < kt) load_stage(nxt % STAGES, nxt);
        CP_COMMIT();

        const uint32_t sA = sbase + (uint32_t)(it % STAGES) * STAGE_BYTES;
        const uint32_t sB = sA + A_STAGE_HALFS * 2;

        #pragma unroll
        for (int kk = 0; kk < BK / 16; ++kk) {   // 4 k-steps of 16
            const uint32_t cb = (uint32_t)(kk << 1);   // chunk base = kb/8

            uint32_t afr[4][4];
            #pragma unroll
            for (int i = 0; i < 4; ++i) {
                const int row = a_row_base + i * 16;
                const uint32_t addr = sA + (uint32_t)(row << 7)
                                    + (((cb + a_cadd) ^ (uint32_t)(row & 7)) << 4);
                ldsm_x4(afr[i], addr);
            }
            uint32_t bfr[8][2];
            #pragma unroll
            for (int jp = 0; jp < 4; ++jp) {
                const int n = b_row_base + jp * 16;
                const uint32_t addr = sB + (uint32_t)(n << 7)
                                    + (((cb + b_cadd) ^ (uint32_t)(n & 7)) << 4);
                uint32_t q[4];
                ldsm_x4(q, addr);
                bfr[2*jp][0]   = q[0]; bfr[2*jp][1]   = q[1];
                bfr[2*jp+1][0] = q[2]; bfr[2*jp+1][1] = q[3];
            }
            #pragma unroll
            for (int i = 0; i < 4; ++i)
                #pragma unroll
                for (int j = 0; j < 8; ++j)
                    mma_f16(acc[i][j], afr[i], bfr[j]);
        }
    }

    // ---------------- epilogue: bias + relu, store fp16 (or fp32 final) --------
    #pragma unroll
    for (int j = 0; j < 8; ++j) {
        const int col = n0 + wn * 64 + j * 8 + t2;
        float b0 = __ldg(bias + col);
        float b1 = __ldg(bias + col + 1);
        if (HASB2) { b0 += __ldg(bias2 + col); b1 += __ldg(bias2 + col + 1); }
        #pragma unroll
        for (int i = 0; i < 4; ++i) {
            const int row0 = m0 + wm * 64 + i * 16 + g;
            float v00 = acc[i][j][0] + b0, v01 = acc[i][j][1] + b1;
            float v10 = acc[i][j][2] + b0, v11 = acc[i][j][3] + b1;
            if (RELU) {
                v00 = fmaxf(v00, 0.0f); v01 = fmaxf(v01, 0.0f);
                v10 = fmaxf(v10, 0.0f); v11 = fmaxf(v11, 0.0f);
            }
            if (OUT32) {
                float* C = (float*)Cv;
                *reinterpret_cast<float2*>(C + (size_t)row0 * ldc + col) =
                    make_float2(v00, v01);
                *reinterpret_cast<float2*>(C + (size_t)(row0 + 8) * ldc + col) =
                    make_float2(v10, v11);
            } else {
                __half* C = (__half*)Cv;
                *reinterpret_cast<__half2*>(C + (size_t)row0 * ldc + col) =
                    __floats2half2_rn(v00, v01);
                *reinterpret_cast<__half2*>(C + (size_t)(row0 + 8) * ldc + col) =
                    __floats2half2_rn(v10, v11);
            }
        }
    }
}

// ---------------- host ----------------
extern "C" void kernel_launch(void* const* d_in, const int* in_sizes, int n_in,
                              void* d_out, int out_size) {
    (void)in_sizes; (void)n_in; (void)out_size;
    const float* x       = (const float*)d_in[0];
    const float* W_init  = (const float*)d_in[1];
    const float* b_init  = (const float*)d_in[2];
    const float* W_ih    = (const float*)d_in[3];
    const float* b_ih    = (const float*)d_in[4];
    const float* b_hh    = (const float*)d_in[5];
    const float* W_final = (const float*)d_in[6];
    const float* b_final = (const float*)d_in[7];
    float* y = (float*)d_out;

    __half *xh, *h, *s2, *w1, *w2, *w3;
    cudaGetSymbolAddress((void**)&xh, g_xh);
    cudaGetSymbolAddress((void**)&h,  g_h);
    cudaGetSymbolAddress((void**)&s2, g_s2);
    cudaGetSymbolAddress((void**)&w1, g_w1);
    cudaGetSymbolAddress((void**)&w2, g_w2);
    cudaGetSymbolAddress((void**)&w3, g_w3);

    cudaFuncSetAttribute(gemm_f16<true,  false, false>,
                         cudaFuncAttributeMaxDynamicSharedMemorySize, SMEM_BYTES);
    cudaFuncSetAttribute(gemm_f16<true,  true,  false>,
                         cudaFuncAttributeMaxDynamicSharedMemorySize, SMEM_BYTES);
    cudaFuncSetAttribute(gemm_f16<false, false, true>,
                         cudaFuncAttributeMaxDynamicSharedMemorySize, SMEM_BYTES);

    // fp32 -> fp16 RNE conversions (this IS the input rounding)
    k_f32_to_f16<<<2048, 256>>>((const float4*)x,       (uint2*)xh, (G_M   * G_DIN) / 4);
    k_f32_to_f16<<<1024, 256>>>((const float4*)W_init,  (uint2*)w1, (G_DH  * G_DIN) / 4);
    k_f32_to_f16<<<1024, 256>>>((const float4*)W_ih,    (uint2*)w2, (G_DH  * G_DH ) / 4);
    k_f32_to_f16<<<1024, 256>>>((const float4*)W_final, (uint2*)w3, (G_DACT* G_DH ) / 4);

    // GEMM1: h = relu(x @ W_init^T + b_init)
    gemm_f16<true, false, false>
        <<<dim3(G_DH / BN, G_M / BM), NTHREADS, SMEM_BYTES>>>(
        xh, w1, b_init, nullptr, h, G_DIN, G_DH);
    // GEMM2: out = relu(h @ W_ih^T + b_ih + b_hh)
    gemm_f16<true, true, false>
        <<<dim3(G_DH / BN, G_M / BM), NTHREADS, SMEM_BYTES>>>(
        h, w2, b_ih, b_hh, s2, G_DH, G_DH);
    // GEMM3: y = out @ W_final^T + b_final   (fp32 output)
    gemm_f16<false, false, true>
        <<<dim3(G_DACT / BN, G_M / BM), NTHREADS, SMEM_BYTES>>>(
        s2, w3, b_final, nullptr, y, G_DH, G_DACT);
}

// round 14
// speedup vs baseline: 1.1540x; 1.1540x over previous
#include <cuda_runtime.h>
#include <cuda_fp16.h>
#include <cstdint>
#include <cstddef>

// ---------------- problem sizes ----------------
#define G_M    32768            // B*S = 16*2048
#define G_DIN  1024
#define G_DH   2048
#define G_DACT 1024

// ---------------- GEMM tiling ----------------
#define BM 128
#define BN 128
#define BK 64                   // halves per K-slice: 128 bytes/row
#define STAGES 3
#define NTHREADS 128            // 4 warps, 2(m) x 2(n), warp tile 64x64

#define A_STAGE_HALFS (BM*BK)             // 8192 halves = 16 KB
#define STAGE_HALFS   (2*BM*BK)           // A then B
#define STAGE_BYTES   (STAGE_HALFS*2)     // 32768
#define SMEM_BYTES    (STAGES*STAGE_BYTES)// 98304

// ---------------- scratch (no cudaMalloc allowed) ----------------
__device__ __align__(16) __half g_xh [(size_t)G_M * G_DIN];     // 64 MB
__device__ __align__(16) __half g_h  [(size_t)G_M * G_DH];      // 128 MB
__device__ __align__(16) __half g_s2 [(size_t)G_M * G_DH];      // 128 MB
__device__ __align__(16) __half g_w1 [(size_t)G_DH * G_DIN];
__device__ __align__(16) __half g_w2 [(size_t)G_DH * G_DH];
__device__ __align__(16) __half g_w3 [(size_t)G_DACT * G_DH];

// ---------------- PTX helpers (base ISA only — no tcgen05 on .target sm_103) ----
__device__ __forceinline__ uint32_t smem_u32(const void* p) {
    uint32_t a;
    asm("{ .reg .u64 t; cvta.to.shared.u64 t, %1; cvt.u32.u64 %0, t; }" : "=r"(a) : "l"(p));
    return a;
}

#define CP_ASYNC16(sm, g) \
    asm volatile("cp.async.cg.shared.global [%0], [%1], 16;" :: "r"(sm), "l"(g))
#define CP_COMMIT() asm volatile("cp.async.commit_group;" ::: "memory")
#define CP_WAIT(n)  asm volatile("cp.async.wait_group %0;" :: "n"(n) : "memory")

// mma.sync m16n8k16 fp16 -> fp32 accumulate. Base ISA (sm_80+), legal on sm_103.
__device__ __forceinline__ void mma_f16(float* d, const uint32_t* a, const uint32_t* b) {
    asm volatile(
        "mma.sync.aligned.m16n8k16.row.col.f32.f16.f16.f32 "
        "{%0,%1,%2,%3}, {%4,%5,%6,%7}, {%8,%9}, {%0,%1,%2,%3};"
        : "+f"(d[0]), "+f"(d[1]), "+f"(d[2]), "+f"(d[3])
        : "r"(a[0]), "r"(a[1]), "r"(a[2]), "r"(a[3]), "r"(b[0]), "r"(b[1]));
}

// ldmatrix x4: 4 m8n8 fp16 matrices; lane L supplies row address for matrix L/8, row L%8.
__device__ __forceinline__ void ldsm_x4(uint32_t* r, uint32_t addr) {
    asm volatile(
        "ldmatrix.sync.aligned.m8n8.x4.shared.b16 {%0,%1,%2,%3}, [%4];"
        : "=r"(r[0]), "=r"(r[1]), "=r"(r[2]), "=r"(r[3]) : "r"(addr));
}

// ---------------- fp32 -> fp16 (RNE) conversion ----------------
__global__ void k_f32_to_f16(const float4* __restrict__ in, uint2* __restrict__ out, int n4) {
    for (int i = blockIdx.x * blockDim.x + threadIdx.x; i < n4; i += gridDim.x * blockDim.x) {
        float4 v = in[i];
        __half2 lo = __floats2half2_rn(v.x, v.y);
        __half2 hi = __floats2half2_rn(v.z, v.w);
        uint2 o;
        o.x = *reinterpret_cast<uint32_t*>(&lo);
        o.y = *reinterpret_cast<uint32_t*>(&hi);
        out[i] = o;
    }
}

// ---- fp16 mma.sync GEMM: C[M,N] = A[M,K] @ Bw[N,K]^T (+bias[,+bias2], relu) ----
// Block tile 128x128, 4 warps in 2(m) x 2(n), warp tile 64x64, occupancy 2.
// OUT32=false: C is __half (RNE convert = rounding for the next GEMM's inputs).
// OUT32=true : C is float (final output).
template<bool RELU, bool HASB2, bool OUT32>
__global__ void __launch_bounds__(NTHREADS, 2)
gemm_f16(const __half* __restrict__ A, const __half* __restrict__ Bw,
         const float* __restrict__ bias, const float* __restrict__ bias2,
         void* __restrict__ Cv, int K, int ldc)
{
    extern __shared__ __half smem[];
    const uint32_t sbase = smem_u32(smem);
    const int tid = threadIdx.x;
    const int wid = tid >> 5;
    const int lid = tid & 31;
    const int m0 = blockIdx.y * BM;
    const int n0 = blockIdx.x * BN;
    const int kt = K / BK;

    // warp grid 2(m) x 2(n): warp tile 64m x 64n
    const int wm  = wid >> 1;         // 0..1
    const int wn  = wid & 1;          // 0..1
    const int g   = lid >> 2;         // 0..7
    const int tig = lid & 3;          // 0..3
    const int t2  = tig << 1;

    // ---- ldmatrix per-lane row precompute ----
    const int mi   = lid >> 3;        // matrix index 0..3
    const int mrow = lid & 7;         // row within matrix
    // A x4 (per i): {rows+0..7 klo, rows+8..15 klo, rows+0..7 khi, rows+8..15 khi}
    const int a_row_base = wm * 64 + ((mi & 1) << 3) + mrow;
    const uint32_t a_cadd = (uint32_t)(mi >> 1);
    // B x4 (per jp in 0..3): {j0 klo, j0 khi, j1 klo, j1 khi}
    const int b_row_base = wn * 64 + ((mi >> 1) << 3) + mrow;
    const uint32_t b_cadd = (uint32_t)(mi & 1);

    // loader mapping: 128 threads -> 16 rows x 8 chunks(16B) per pass
    const int lr = tid >> 3;          // 0..15
    const int lc = tid & 7;           // 0..7

    auto load_stage = [&](int slot, int it) {
        const int k0 = it * BK;
        const uint32_t sA = sbase + (uint32_t)slot * STAGE_BYTES;
        const uint32_t sB = sA + A_STAGE_HALFS * 2;
        const __half* gA = A  + (size_t)(m0 + lr) * K + k0 + (lc << 3);
        const __half* gB = Bw + (size_t)(n0 + lr) * K + k0 + (lc << 3);
        #pragma unroll
        for (int j = 0; j < BM / 16; ++j) {      // 8 passes of 16 rows each
            const int row = lr + 16 * j;
            const uint32_t off = (uint32_t)(row * 128 + ((lc ^ (row & 7)) << 4));
            CP_ASYNC16(sA + off, gA + (size_t)(16 * j) * K);
            CP_ASYNC16(sB + off, gB + (size_t)(16 * j) * K);
        }
    };

    float acc[4][8][4];
    #pragma unroll
    for (int i = 0; i < 4; ++i)
        #pragma unroll
        for (int j = 0; j < 8; ++j)
            #pragma unroll
            for (int e = 0; e < 4; ++e) acc[i][j][e] = 0.0f;

    #pragma unroll
    for (int s = 0; s < STAGES - 1; ++s) { load_stage(s, s); CP_COMMIT(); }

    for (int it = 0; it < kt; ++it) {
        CP_WAIT(STAGES - 2);
        __syncthreads();

        const int nxt = it + STAGES - 1;
        if (nxt < kt) load_stage(nxt % STAGES, nxt);
        CP_COMMIT();

        const uint32_t sA = sbase + (uint32_t)(it % STAGES) * STAGE_BYTES;
        const uint32_t sB = sA + A_STAGE_HALFS * 2;

        #pragma unroll
        for (int kk = 0; kk < BK / 16; ++kk) {   // 4 k-steps of 16
            const uint32_t cb = (uint32_t)(kk << 1);   // chunk base = kb/8

            uint32_t afr[4][4];
            #pragma unroll
            for (int i = 0; i < 4; ++i) {
                const int row = a_row_base + i * 16;
                const uint32_t addr = sA + (uint32_t)(row << 7)
                                    + (((cb + a_cadd) ^ (uint32_t)(row & 7)) << 4);
                ldsm_x4(afr[i], addr);
            }
            uint32_t bfr[8][2];
            #pragma unroll
            for (int jp = 0; jp < 4; ++jp) {
                const int n = b_row_base + jp * 16;
                const uint32_t addr = sB + (uint32_t)(n << 7)
                                    + (((cb + b_cadd) ^ (uint32_t)(n & 7)) << 4);
                uint32_t q[4];
                ldsm_x4(q, addr);
                bfr[2*jp][0]   = q[0]; bfr[2*jp][1]   = q[1];
                bfr[2*jp+1][0] = q[2]; bfr[2*jp+1][1] = q[3];
            }
            #pragma unroll
            for (int i = 0; i < 4; ++i)
                #pragma unroll
                for (int j = 0; j < 8; ++j)
                    mma_f16(acc[i][j], afr[i], bfr[j]);
        }
    }

    // ---------------- epilogue: bias + relu, store fp16 (or fp32 final) --------
    #pragma unroll
    for (int j = 0; j < 8; ++j) {
        const int col = n0 + wn * 64 + j * 8 + t2;
        float b0 = __ldg(bias + col);
        float b1 = __ldg(bias + col + 1);
        if (HASB2) { b0 += __ldg(bias2 + col); b1 += __ldg(bias2 + col + 1); }
        #pragma unroll
        for (int i = 0; i < 4; ++i) {
            const int row0 = m0 + wm * 64 + i * 16 + g;
            float v00 = acc[i][j][0] + b0, v01 = acc[i][j][1] + b1;
            float v10 = acc[i][j][2] + b0, v11 = acc[i][j][3] + b1;
            if (RELU) {
                v00 = fmaxf(v00, 0.0f); v01 = fmaxf(v01, 0.0f);
                v10 = fmaxf(v10, 0.0f); v11 = fmaxf(v11, 0.0f);
            }
            if (OUT32) {
                float* C = (float*)Cv;
                *reinterpret_cast<float2*>(C + (size_t)row0 * ldc + col) =
                    make_float2(v00, v01);
                *reinterpret_cast<float2*>(C + (size_t)(row0 + 8) * ldc + col) =
                    make_float2(v10, v11);
            } else {
                __half* C = (__half*)Cv;
                *reinterpret_cast<__half2*>(C + (size_t)row0 * ldc + col) =
                    __floats2half2_rn(v00, v01);
                *reinterpret_cast<__half2*>(C + (size_t)(row0 + 8) * ldc + col) =
                    __floats2half2_rn(v10, v11);
            }
        }
    }
}

// ---------------- host ----------------
extern "C" void kernel_launch(void* const* d_in, const int* in_sizes, int n_in,
                              void* d_out, int out_size) {
    (void)in_sizes; (void)n_in; (void)out_size;
    const float* x       = (const float*)d_in[0];
    const float* W_init  = (const float*)d_in[1];
    const float* b_init  = (const float*)d_in[2];
    const float* W_ih    = (const float*)d_in[3];
    const float* b_ih    = (const float*)d_in[4];
    const float* b_hh    = (const float*)d_in[5];
    const float* W_final = (const float*)d_in[6];
    const float* b_final = (const float*)d_in[7];
    float* y = (float*)d_out;

    __half *xh, *h, *s2, *w1, *w2, *w3;
    cudaGetSymbolAddress((void**)&xh, g_xh);
    cudaGetSymbolAddress((void**)&h,  g_h);
    cudaGetSymbolAddress((void**)&s2, g_s2);
    cudaGetSymbolAddress((void**)&w1, g_w1);
    cudaGetSymbolAddress((void**)&w2, g_w2);
    cudaGetSymbolAddress((void**)&w3, g_w3);

    cudaFuncSetAttribute(gemm_f16<true,  false, false>,
                         cudaFuncAttributeMaxDynamicSharedMemorySize, SMEM_BYTES);
    cudaFuncSetAttribute(gemm_f16<true,  true,  false>,
                         cudaFuncAttributeMaxDynamicSharedMemorySize, SMEM_BYTES);
    cudaFuncSetAttribute(gemm_f16<false, false, true>,
                         cudaFuncAttributeMaxDynamicSharedMemorySize, SMEM_BYTES);

    // fp32 -> fp16 RNE conversions (this IS the input rounding)
    k_f32_to_f16<<<2048, 256>>>((const float4*)x,       (uint2*)xh, (G_M   * G_DIN) / 4);
    k_f32_to_f16<<<1024, 256>>>((const float4*)W_init,  (uint2*)w1, (G_DH  * G_DIN) / 4);
    k_f32_to_f16<<<1024, 256>>>((const float4*)W_ih,    (uint2*)w2, (G_DH  * G_DH ) / 4);
    k_f32_to_f16<<<1024, 256>>>((const float4*)W_final, (uint2*)w3, (G_DACT* G_DH ) / 4);

    // GEMM1: h = relu(x @ W_init^T + b_init)
    gemm_f16<true, false, false>
        <<<dim3(G_DH / BN, G_M / BM), NTHREADS, SMEM_BYTES>>>(
        xh, w1, b_init, nullptr, h, G_DIN, G_DH);
    // GEMM2: out = relu(h @ W_ih^T + b_ih + b_hh)
    gemm_f16<true, true, false>
        <<<dim3(G_DH / BN, G_M / BM), NTHREADS, SMEM_BYTES>>>(
        h, w2, b_ih, b_hh, s2, G_DH, G_DH);
    // GEMM3: y = out @ W_final^T + b_final   (fp32 output)
    gemm_f16<false, false, true>
        <<<dim3(G_DACT / BN, G_M / BM), NTHREADS, SMEM_BYTES>>>(
        s2, w3, b_final, nullptr, y, G_DH, G_DACT);
}